// round 5
// baseline (speedup 1.0000x reference)
#include <cuda_runtime.h>
#include <math.h>

// Fused: conv2d(3->16,3x3,pad1)+GELU(exact) -> conv2d(16->18,3x3,pad1) -> 9-tap
// deformable bilinear sampling of pm25 with per-tap offsets (dy=ch 2k, dx=ch 2k+1).
//
// Tile: 32 wide x 16 tall, block 16x16 = 256 threads, TWO output pixels per
// thread (x-pair). Phase 3 computes the 18 offset channels in two passes
// (10 then 8 channels) so each pass ends on a complete (dy,dx) tap pair:
//   pass A: channels 0..9  -> taps 0..4, pass B: channels 10..17 -> taps 5..8.
// Caps live accumulators at 20 floats; never splits a tap; no recompute.

#define TW 32
#define TH 16
#define BX 16
#define BY 16
#define NTHREADS (BX * BY)   // 256
#define IN_H (TH + 4)        // 20
#define IN_W (TW + 4)        // 36
#define HH   (TH + 2)        // 18
#define HW_  (TW + 2)        // 34

__constant__ float c_w1[16 * 27]; // [co][ci*9+t]
__constant__ float c_b1[16];
__constant__ float c_w2[18 * 16 * 9]; // [co][ci][t]
__constant__ float c_b2[18];
__constant__ float c_wd[9];

__device__ __forceinline__ float bilin_tap(float dy, float dx, int k,
                                           int x, int y,
                                           const float* __restrict__ img,
                                           int H, int W)
{
    const float kyf = (float)(k / 3 - 1);
    const float kxf = (float)(k % 3 - 1);
    float py = (float)y + kyf + dy;
    float px = (float)x + kxf + dx;
    float y0f = floorf(py);
    float x0f = floorf(px);
    float wy1 = py - y0f;
    float wx1 = px - x0f;
    int y0 = (int)y0f;
    int x0 = (int)x0f;
    bool yv0 = (y0 >= 0) && (y0 < H);
    bool yv1 = (y0 + 1 >= 0) && (y0 + 1 < H);
    bool xv0 = (x0 >= 0) && (x0 < W);
    bool xv1 = (x0 + 1 >= 0) && (x0 + 1 < W);
    float v00 = 0.f, v01 = 0.f, v10 = 0.f, v11 = 0.f;
    if (yv0 && xv0) v00 = img[(size_t)y0 * W + x0];
    if (yv0 && xv1) v01 = img[(size_t)y0 * W + x0 + 1];
    if (yv1 && xv0) v10 = img[(size_t)(y0 + 1) * W + x0];
    if (yv1 && xv1) v11 = img[(size_t)(y0 + 1) * W + x0 + 1];
    float wy0 = 1.0f - wy1;
    float wx0 = 1.0f - wx1;
    return wy0 * wx0 * v00 + wy0 * wx1 * v01
         + wy1 * wx0 * v10 + wy1 * wx1 * v11;
}

__global__ __launch_bounds__(NTHREADS, 2)
void residual_advection_fused(
    const float* __restrict__ pm25,  // [B,1,H,W]
    const float* __restrict__ wind,  // [B,2,H,W]
    const float* __restrict__ topo,  // [B,1,H,W]
    float* __restrict__ out,         // [B,1,H,W]
    int B, int H, int W)
{
    __shared__ float s_in[3][IN_H][IN_W];
    __shared__ float s_h[16][HH][HW_];

    const int b   = blockIdx.z;
    const int gx0 = blockIdx.x * TW;
    const int gy0 = blockIdx.y * TH;
    const int tx  = threadIdx.x;     // 0..15 (pixel pair index)
    const int ty  = threadIdx.y;     // 0..15
    const int tid = ty * BX + tx;

    // ---------------- Phase 1: load offset_input tile + halo 2 ----------------
    for (int idx = tid; idx < 3 * IN_H * IN_W; idx += NTHREADS) {
        int ci  = idx / (IN_H * IN_W);
        int rem = idx - ci * (IN_H * IN_W);
        int r = rem / IN_W;
        int c = rem - r * IN_W;
        int gy = gy0 + r - 2;
        int gx = gx0 + c - 2;
        float v = 0.f;
        if (gy >= 0 && gy < H && gx >= 0 && gx < W) {
            if (ci < 2) v = wind[(((size_t)b * 2 + ci) * H + gy) * W + gx];
            else        v = topo[((size_t)b * H + gy) * W + gx];
        }
        s_in[ci][r][c] = v;
    }
    __syncthreads();

    // ---------------- Phase 2: h = gelu(conv1(in)) over tile + halo 1 ---------
    for (int hidx = tid; hidx < HH * HW_; hidx += NTHREADS) {
        int r = hidx / HW_;
        int c = hidx - r * HW_;
        int gy = gy0 + r - 1;
        int gx = gx0 + c - 1;
        if (gy < 0 || gy >= H || gx < 0 || gx >= W) {
            #pragma unroll
            for (int co = 0; co < 16; co++) s_h[co][r][c] = 0.f;
        } else {
            float iv[27];
            #pragma unroll
            for (int ci = 0; ci < 3; ci++)
                #pragma unroll
                for (int ky = 0; ky < 3; ky++)
                    #pragma unroll
                    for (int kx = 0; kx < 3; kx++)
                        iv[ci * 9 + ky * 3 + kx] = s_in[ci][r + ky][c + kx];
            #pragma unroll
            for (int co = 0; co < 16; co++) {
                float a = c_b1[co];
                #pragma unroll
                for (int t = 0; t < 27; t++)
                    a = fmaf(iv[t], c_w1[co * 27 + t], a);
                // exact GELU: 0.5 * a * (1 + erf(a / sqrt(2)))
                s_h[co][r][c] = 0.5f * a * (1.0f + erff(a * 0.7071067811865476f));
            }
        }
    }
    __syncthreads();

    // ------- Phase 3+4: offsets = conv2(h) in passes of 10 then 8 channels, ---
    // ------- each followed by deformable bilinear sampling of its taps.     ---
    const int y   = gy0 + ty;
    const int x0p = gx0 + 2 * tx;
    const float* img = pm25 + (size_t)b * H * W;

    float r0 = 0.f, r1 = 0.f;

    #pragma unroll
    for (int pass = 0; pass < 2; pass++) {
        const int co0 = (pass == 0) ? 0 : 10;   // first channel of this pass
        const int nco = (pass == 0) ? 10 : 8;   // channels in this pass
        const int k0  = co0 / 2;                // first tap of this pass
        const int nk  = nco / 2;                // taps in this pass

        float acc0[10], acc1[10];
        #pragma unroll
        for (int j = 0; j < 10; j++) {
            if (j < nco) { acc0[j] = c_b2[co0 + j]; acc1[j] = c_b2[co0 + j]; }
        }

        #pragma unroll
        for (int ci = 0; ci < 16; ci++) {
            float hv[3][4];
            #pragma unroll
            for (int ky = 0; ky < 3; ky++) {
                // 4 consecutive floats, 8B-aligned (2*tx even, row stride 34 even)
                const float* row = &s_h[ci][ty + ky][2 * tx];
                float2 lo = *reinterpret_cast<const float2*>(row);
                float2 hi = *reinterpret_cast<const float2*>(row + 2);
                hv[ky][0] = lo.x; hv[ky][1] = lo.y; hv[ky][2] = hi.x; hv[ky][3] = hi.y;
            }
            #pragma unroll
            for (int j = 0; j < 10; j++) {
                if (j < nco) {
                    #pragma unroll
                    for (int t = 0; t < 9; t++) {
                        const int ky = t / 3, kx = t % 3;
                        const float w = c_w2[((co0 + j) * 16 + ci) * 9 + t];
                        acc0[j] = fmaf(hv[ky][kx],     w, acc0[j]);
                        acc1[j] = fmaf(hv[ky][kx + 1], w, acc1[j]);
                    }
                }
            }
        }

        #pragma unroll
        for (int kk = 0; kk < 5; kk++) {
            if (kk < nk) {
                const int k = k0 + kk;
                r0 = fmaf(bilin_tap(acc0[2*kk], acc0[2*kk+1], k, x0p,     y, img, H, W), c_wd[k], r0);
                r1 = fmaf(bilin_tap(acc1[2*kk], acc1[2*kk+1], k, x0p + 1, y, img, H, W), c_wd[k], r1);
            }
        }
    }

    float2* o2 = reinterpret_cast<float2*>(out + ((size_t)b * H + y) * W + x0p);
    *o2 = make_float2(r0, r1);
}

extern "C" void kernel_launch(void* const* d_in, const int* in_sizes, int n_in,
                              void* d_out, int out_size) {
    const float* pm25 = (const float*)d_in[0];
    const float* wind = (const float*)d_in[1];
    const float* topo = (const float*)d_in[2];

    const int H = 512, W = 512;
    const int B = in_sizes[0] / (H * W);

    cudaMemcpyToSymbolAsync(c_w1, d_in[3], 16 * 27 * sizeof(float),     0, cudaMemcpyDeviceToDevice);
    cudaMemcpyToSymbolAsync(c_b1, d_in[4], 16 * sizeof(float),          0, cudaMemcpyDeviceToDevice);
    cudaMemcpyToSymbolAsync(c_w2, d_in[5], 18 * 16 * 9 * sizeof(float), 0, cudaMemcpyDeviceToDevice);
    cudaMemcpyToSymbolAsync(c_b2, d_in[6], 18 * sizeof(float),          0, cudaMemcpyDeviceToDevice);
    cudaMemcpyToSymbolAsync(c_wd, d_in[7], 9 * sizeof(float),           0, cudaMemcpyDeviceToDevice);

    dim3 grid(W / TW, H / TH, B);
    dim3 blk(BX, BY);
    residual_advection_fused<<<grid, blk>>>(pm25, wind, topo, (float*)d_out, B, H, W);
}